// round 11
// baseline (speedup 1.0000x reference)
#include <cuda_runtime.h>
#include <cstdint>

#define DIM 128
#define HID 64
#define MAX_TISSUE 4096
#define TILE 16
#define NW 8     // warps per CTA
#define SWS 132  // padded float stride, Wc (tf32 bits)

// scratch: projected tissue keys (+ both biases folded in)
__device__ float g_tkb[MAX_TISSUE * HID];

// ---------------------------------------------------------------------------
// Kernel A: tkb[t][h] = bt[h] + bc[h] + sum_d Wt[h][d] * tissue[t][d]
// ---------------------------------------------------------------------------
__global__ void tissue_proj_kernel(const float* __restrict__ tissue,
                                   const float* __restrict__ Wt,
                                   const float* __restrict__ bt,
                                   const float* __restrict__ bc,
                                   int n_tissue) {
    __shared__ float st[16][DIM];
    __shared__ float swt[HID][DIM + 4];
    int tid = threadIdx.x;
    int t0 = blockIdx.x * 16;

    for (int i = tid; i < HID * (DIM / 4); i += 256) {
        int h = i >> 5, c = i & 31;
        float4 v = ((const float4*)Wt)[h * 32 + c];
        *(float4*)&swt[h][c * 4] = v;
    }
    for (int i = tid; i < 16 * 32; i += 256) {
        int r = i >> 5, c = i & 31;
        float4 v = make_float4(0.f, 0.f, 0.f, 0.f);
        if (t0 + r < n_tissue) v = ((const float4*)tissue)[(size_t)(t0 + r) * 32 + c];
        *(float4*)&st[r][c * 4] = v;
    }
    __syncthreads();

    #pragma unroll
    for (int j = 0; j < 4; j++) {
        int o = tid + j * 256;
        int tl = o >> 6, h = o & 63;
        if (t0 + tl >= n_tissue) continue;
        float acc = bt[h] + bc[h];
        #pragma unroll 8
        for (int c = 0; c < 32; c++) {
            float4 w = *(const float4*)&swt[h][c * 4];
            float4 x = *(const float4*)&st[tl][c * 4];
            acc += w.x * x.x + w.y * x.y + w.z * x.z + w.w * x.w;
        }
        g_tkb[(size_t)(t0 + tl) * HID + h] = acc;
    }
}

// ---------------------------------------------------------------------------
__device__ __forceinline__ unsigned f2tf32(float x) {
    unsigned r;
    asm("cvt.rna.tf32.f32 %0, %1;" : "=r"(r) : "f"(x));
    return r;
}
__device__ __forceinline__ float tanh_ap(float x) {
    float y;
    asm("tanh.approx.f32 %0, %1;" : "=f"(y) : "f"(x));
    return y;
}
__device__ __forceinline__ void ldm_x4(unsigned* r, unsigned saddr) {
    asm volatile("ldmatrix.sync.aligned.m8n8.x4.shared.b16 {%0,%1,%2,%3}, [%4];"
                 : "=r"(r[0]), "=r"(r[1]), "=r"(r[2]), "=r"(r[3])
                 : "r"(saddr));
}

extern __shared__ float smem[];

// ---------------------------------------------------------------------------
// Kernel B: warp-autonomous, persistent, NO smem staging for X.
// A-fragments loaded directly from GMEM (registers); residual X re-read from
// L1-hot lines; B (Wc) from a constant smem tile via ldmatrix.
// ---------------------------------------------------------------------------
__global__ __launch_bounds__(256, 1)
void fuse_kernel(const float* __restrict__ cellf,
                 const float* __restrict__ tissuef,
                 const int* __restrict__ c2t,
                 const float* __restrict__ Wc,
                 const float* __restrict__ attnw,
                 float* __restrict__ out,
                 int n_cell, int ntiles) {
    unsigned* swc = (unsigned*)smem;   // 64*SWS tf32 bits (constant after init)

    int tid = threadIdx.x;
    int wid = tid >> 5, lane = tid & 31;
    int gid = lane >> 2, tig = lane & 3;
    int lml = lane & 7, lmm = lane >> 3;

    // ---- one-time staging: Wc as tf32 ----
    for (int i = tid; i < 64 * 32; i += 256) {
        int r = i >> 5, c = i & 31;
        float4 v = ((const float4*)Wc)[r * 32 + c];
        uint4 w;
        w.x = f2tf32(v.x); w.y = f2tf32(v.y); w.z = f2tf32(v.z); w.w = f2tf32(v.w);
        *(uint4*)&swc[r * SWS + c * 4] = w;
    }
    __syncthreads();   // only block barrier

    // attn weights register-resident (cols nt*8 + 2*tig, +1)
    float aw[8][2];
    #pragma unroll
    for (int nt = 0; nt < 8; nt++) {
        float2 v = ((const float2*)attnw)[nt * 4 + tig];
        aw[nt][0] = v.x; aw[nt][1] = v.y;
    }

    unsigned swc_u = (unsigned)__cvta_generic_to_shared(swc);
    unsigned b_off = swc_u + ((unsigned)(lml * SWS + lmm * 4)) * 4u;

    int stride = gridDim.x * NW;
    int t0w = blockIdx.x * NW + wid;

    auto load_ids = [&](int t) -> int {
        int row = t * TILE + (lane & 15);
        return c2t[row < n_cell ? row : 0];
    };

    int idc = (t0w < ntiles) ? load_ids(t0w) : 0;

    for (int t = t0w; t < ntiles; t += stride) {
        int tn = t + stride;
        int idn = (tn < ntiles) ? load_ids(tn) : 0;   // prefetch next ids

        // ---- direct-LDG A fragments: rows rlo=t*16+gid, rhi=+8 ----
        int rlo = t * TILE + gid;
        int rhi = rlo + 8;
        const float* xlo = cellf + (size_t)(rlo < n_cell ? rlo : n_cell - 1) * DIM;
        const float* xhi = cellf + (size_t)(rhi < n_cell ? rhi : n_cell - 1) * DIM;
        float alo[32], ahi[32];
        #pragma unroll
        for (int j = 0; j < 16; j++) {          // j = 2p + kk
            alo[2 * j]     = xlo[8 * j + tig];
            alo[2 * j + 1] = xlo[8 * j + tig + 4];
            ahi[2 * j]     = xhi[8 * j + tig];
            ahi[2 * j + 1] = xhi[8 * j + tig + 4];
        }

        // ---- tkb gather (consumed after mma) ----
        int tlo = __shfl_sync(0xffffffffu, idc, gid);
        int thi = __shfl_sync(0xffffffffu, idc, gid + 8);
        float2 klo[8], khi[8];
        {
            const float2* plo = (const float2*)&g_tkb[(size_t)tlo * HID];
            const float2* phi = (const float2*)&g_tkb[(size_t)thi * HID];
            #pragma unroll
            for (int nt = 0; nt < 8; nt++) {
                klo[nt] = plo[nt * 4 + tig];
                khi[nt] = phi[nt * 4 + tig];
            }
        }

        // ---- Q = X @ Wc^T : A from registers (raw fp32 bits = RZ tf32) ----
        float acc[8][4];
        #pragma unroll
        for (int nt = 0; nt < 8; nt++) {
            acc[nt][0] = 0.f; acc[nt][1] = 0.f; acc[nt][2] = 0.f; acc[nt][3] = 0.f;
        }
        #pragma unroll
        for (int p = 0; p < 8; p++) {
            unsigned a00 = __float_as_uint(alo[4 * p]);
            unsigned a01 = __float_as_uint(ahi[4 * p]);
            unsigned a02 = __float_as_uint(alo[4 * p + 1]);
            unsigned a03 = __float_as_uint(ahi[4 * p + 1]);
            unsigned a10 = __float_as_uint(alo[4 * p + 2]);
            unsigned a11 = __float_as_uint(ahi[4 * p + 2]);
            unsigned a12 = __float_as_uint(alo[4 * p + 3]);
            unsigned a13 = __float_as_uint(ahi[4 * p + 3]);
            #pragma unroll
            for (int nt = 0; nt < 8; nt++) {
                unsigned b[4];
                ldm_x4(b, b_off + (unsigned)(nt * 8 * SWS) * 4u + (unsigned)(p * 64));
                asm volatile(
                    "mma.sync.aligned.m16n8k8.row.col.f32.tf32.tf32.f32 "
                    "{%0,%1,%2,%3}, {%4,%5,%6,%7}, {%8,%9}, {%0,%1,%2,%3};\n"
                    : "+f"(acc[nt][0]), "+f"(acc[nt][1]),
                      "+f"(acc[nt][2]), "+f"(acc[nt][3])
                    : "r"(a00), "r"(a01), "r"(a02), "r"(a03),
                      "r"(b[0]), "r"(b[1]));
                asm volatile(
                    "mma.sync.aligned.m16n8k8.row.col.f32.tf32.tf32.f32 "
                    "{%0,%1,%2,%3}, {%4,%5,%6,%7}, {%8,%9}, {%0,%1,%2,%3};\n"
                    : "+f"(acc[nt][0]), "+f"(acc[nt][1]),
                      "+f"(acc[nt][2]), "+f"(acc[nt][3])
                    : "r"(a10), "r"(a11), "r"(a12), "r"(a13),
                      "r"(b[2]), "r"(b[3]));
            }
        }

        // ---- score = attn . tanh(q + key); quad reduce; gate ----
        float p0 = 0.f, p1 = 0.f;
        #pragma unroll
        for (int nt = 0; nt < 8; nt++) {
            p0 += aw[nt][0] * tanh_ap(acc[nt][0] + klo[nt].x)
                + aw[nt][1] * tanh_ap(acc[nt][1] + klo[nt].y);
            p1 += aw[nt][0] * tanh_ap(acc[nt][2] + khi[nt].x)
                + aw[nt][1] * tanh_ap(acc[nt][3] + khi[nt].y);
        }
        p0 += __shfl_xor_sync(0xffffffffu, p0, 1);
        p0 += __shfl_xor_sync(0xffffffffu, p0, 2);
        p1 += __shfl_xor_sync(0xffffffffu, p1, 1);
        p1 += __shfl_xor_sync(0xffffffffu, p1, 2);
        float g0 = __fdividef(1.f, 1.f + __expf(-p0));
        float g1 = __fdividef(1.f, 1.f + __expf(-p1));

        // ---- epilogue: out = x + tissue[t]*gate ; X re-read (L1-hot) ----
        #pragma unroll
        for (int j = 0; j < TILE; j++) {
            int row = t * TILE + j;
            if (row >= n_cell) break;
            float g = (j < 8) ? __shfl_sync(0xffffffffu, g0, j * 4)
                              : __shfl_sync(0xffffffffu, g1, (j - 8) * 4);
            int tt = __shfl_sync(0xffffffffu, idc, j);
            float4 xv = ((const float4*)cellf)[(size_t)row * 32 + lane];
            float4 tv = ((const float4*)tissuef)[(size_t)tt * 32 + lane];
            float4 o;
            o.x = fmaf(tv.x, g, xv.x);
            o.y = fmaf(tv.y, g, xv.y);
            o.z = fmaf(tv.z, g, xv.z);
            o.w = fmaf(tv.w, g, xv.w);
            ((float4*)out)[(size_t)row * 32 + lane] = o;
        }

        idc = idn;
    }
}

// ---------------------------------------------------------------------------
extern "C" void kernel_launch(void* const* d_in, const int* in_sizes, int n_in,
                              void* d_out, int out_size) {
    const float* cellf   = (const float*)d_in[0];
    const float* tissuef = (const float*)d_in[1];
    const int*   c2t     = (const int*)d_in[2];
    const float* Wt      = (const float*)d_in[3];
    const float* bt      = (const float*)d_in[4];
    const float* Wc      = (const float*)d_in[5];
    const float* bc      = (const float*)d_in[6];
    const float* attnw   = (const float*)d_in[7];
    float* out = (float*)d_out;

    int n_cell   = in_sizes[0] / DIM;
    int n_tissue = in_sizes[1] / DIM;
    int ntiles   = (n_cell + TILE - 1) / TILE;

    tissue_proj_kernel<<<(n_tissue + 15) / 16, 256>>>(tissuef, Wt, bt, bc, n_tissue);

    int dev = 0, sms = 148;
    cudaGetDevice(&dev);
    cudaDeviceGetAttribute(&sms, cudaDevAttrMultiProcessorCount, dev);

    size_t shmem_bytes = (size_t)(64 * SWS) * 4;
    cudaFuncSetAttribute(fuse_kernel,
                         cudaFuncAttributeMaxDynamicSharedMemorySize,
                         (int)shmem_bytes);
    int grid = sms;
    fuse_kernel<<<grid, 256, shmem_bytes>>>(cellf, tissuef, c2t, Wc, attnw,
                                            out, n_cell, ntiles);
}

// round 12
// speedup vs baseline: 1.0973x; 1.0973x over previous
#include <cuda_runtime.h>
#include <cstdint>

#define DIM 128
#define HID 64
#define MAX_TISSUE 4096
#define TILE 32
#define NSTAGE 4
#define SXS 132  // padded float stride, X tile
#define SWS 132  // padded float stride, Wc tile (tf32 bits)

// scratch: projected tissue keys (+ both biases folded in)
__device__ float g_tkb[MAX_TISSUE * HID];

// ---------------------------------------------------------------------------
// Kernel A: tkb[t][h] = bt[h] + bc[h] + sum_d Wt[h][d] * tissue[t][d]
// ---------------------------------------------------------------------------
__global__ void tissue_proj_kernel(const float* __restrict__ tissue,
                                   const float* __restrict__ Wt,
                                   const float* __restrict__ bt,
                                   const float* __restrict__ bc,
                                   int n_tissue) {
    __shared__ float st[16][DIM];
    __shared__ float swt[HID][DIM + 4];
    int tid = threadIdx.x;
    int t0 = blockIdx.x * 16;

    for (int i = tid; i < HID * (DIM / 4); i += 256) {
        int h = i >> 5, c = i & 31;
        float4 v = ((const float4*)Wt)[h * 32 + c];
        *(float4*)&swt[h][c * 4] = v;
    }
    for (int i = tid; i < 16 * 32; i += 256) {
        int r = i >> 5, c = i & 31;
        float4 v = make_float4(0.f, 0.f, 0.f, 0.f);
        if (t0 + r < n_tissue) v = ((const float4*)tissue)[(size_t)(t0 + r) * 32 + c];
        *(float4*)&st[r][c * 4] = v;
    }
    __syncthreads();

    #pragma unroll
    for (int j = 0; j < 4; j++) {
        int o = tid + j * 256;
        int tl = o >> 6, h = o & 63;
        if (t0 + tl >= n_tissue) continue;
        float acc = bt[h] + bc[h];
        #pragma unroll 8
        for (int c = 0; c < 32; c++) {
            float4 w = *(const float4*)&swt[h][c * 4];
            float4 x = *(const float4*)&st[tl][c * 4];
            acc += w.x * x.x + w.y * x.y + w.z * x.z + w.w * x.w;
        }
        g_tkb[(size_t)(t0 + tl) * HID + h] = acc;
    }
}

// ---------------------------------------------------------------------------
__device__ __forceinline__ unsigned f2tf32(float x) {
    unsigned r;
    asm("cvt.rna.tf32.f32 %0, %1;" : "=r"(r) : "f"(x));
    return r;
}
__device__ __forceinline__ float tanh_ap(float x) {
    float y;
    asm("tanh.approx.f32 %0, %1;" : "=f"(y) : "f"(x));
    return y;
}
__device__ __forceinline__ void cp_async16(void* sdst, const void* gsrc, bool pred) {
    unsigned s = (unsigned)__cvta_generic_to_shared(sdst);
    int sz = pred ? 16 : 0;
    asm volatile("cp.async.cg.shared.global [%0], [%1], 16, %2;\n"
                 :: "r"(s), "l"(gsrc), "r"(sz));
}
__device__ __forceinline__ void cp_async4(void* sdst, const void* gsrc, bool pred) {
    unsigned s = (unsigned)__cvta_generic_to_shared(sdst);
    int sz = pred ? 4 : 0;
    asm volatile("cp.async.ca.shared.global [%0], [%1], 4, %2;\n"
                 :: "r"(s), "l"(gsrc), "r"(sz));
}
__device__ __forceinline__ void cp_commit() {
    asm volatile("cp.async.commit_group;\n" ::: "memory");
}
__device__ __forceinline__ void cp_wait3() {
    asm volatile("cp.async.wait_group 3;\n" ::: "memory");
}
__device__ __forceinline__ void ldm_x4(unsigned* r, unsigned saddr) {
    asm volatile("ldmatrix.sync.aligned.m8n8.x4.shared.b16 {%0,%1,%2,%3}, [%4];"
                 : "=r"(r[0]), "=r"(r[1]), "=r"(r[2]), "=r"(r[3])
                 : "r"(saddr));
}

extern __shared__ float smem[];

// ---------------------------------------------------------------------------
// Kernel B: persistent, 4-stage cp.async pipeline (3 tiles always in flight);
// 32-row tiles; 2 CTAs/SM. Warp grid: 2 m-tiles x 4 n-quarters.
// ---------------------------------------------------------------------------
__global__ __launch_bounds__(256, 2)
void fuse_kernel(const float* __restrict__ cellf,
                 const float* __restrict__ tissuef,
                 const int* __restrict__ c2t,
                 const float* __restrict__ Wc,
                 const float* __restrict__ attnw,
                 float* __restrict__ out,
                 int n_cell, int ntiles) {
    float*    sx    = smem;                                   // NSTAGE X bufs
    unsigned* swc   = (unsigned*)(sx + NSTAGE * TILE * SXS);  // 64*132 tf32
    int*      stid  = (int*)(swc + 64 * SWS);                 // NSTAGE * 32
    float*    spart = (float*)(stid + NSTAGE * TILE);         // 4 * 32
    float*    sattn = spart + 4 * TILE;                       // 64

    int tid = threadIdx.x;

    // ---- one-time staging: Wc (tf32) + attn weights ----
    for (int i = tid; i < 64 * 32; i += 256) {
        int r = i >> 5, c = i & 31;
        float4 v = ((const float4*)Wc)[r * 32 + c];
        uint4 w;
        w.x = f2tf32(v.x); w.y = f2tf32(v.y); w.z = f2tf32(v.z); w.w = f2tf32(v.w);
        *(uint4*)&swc[r * SWS + c * 4] = w;
    }
    if (tid < 64) sattn[tid] = attnw[tid];

    int wid = tid >> 5, lane = tid & 31;
    int gid = lane >> 2, tig = lane & 3;
    int wm = wid & 1, wn = wid >> 1;     // 2 m-tiles x 4 n-quarters
    int m0 = wm * 16;
    int rlo = m0 + gid, rhi = m0 + gid + 8;
    int h0 = wn * 16;

    int lml = lane & 7, lmm = lane >> 3;
    unsigned sx_u  = (unsigned)__cvta_generic_to_shared(sx);
    unsigned swc_u = (unsigned)__cvta_generic_to_shared(swc);
    unsigned a_off = ((unsigned)((m0 + (lmm & 1) * 8 + lml) * SXS + (lmm >> 1) * 4)) * 4u;
    unsigned b_off = swc_u + ((unsigned)((h0 + lml) * SWS + lmm * 4)) * 4u;

    // ---- tile issue helper ----
    auto issue_tile = [&](int t, int buf) {
        float* dst = sx + buf * TILE * SXS;
        int base = t * TILE;
        #pragma unroll
        for (int j = 0; j < 4; j++) {
            int i = tid + j * 256;
            int r = i >> 5, c = i & 31;
            int row = base + r;
            bool ok = row < n_cell;
            int rowc = ok ? row : (n_cell - 1);
            cp_async16(&dst[r * SXS + c * 4],
                       cellf + (size_t)rowc * DIM + c * 4, ok);
        }
        if (tid < TILE) {
            int row = base + tid;
            bool ok = row < n_cell;
            int rowc = ok ? row : 0;
            cp_async4(&stid[buf * TILE + tid], c2t + rowc, ok);
        }
    };

    int t0 = blockIdx.x;
    // prologue: 3 stages in flight (unconditional commits keep accounting exact)
    #pragma unroll
    for (int s = 0; s < NSTAGE - 1; s++) {
        int ts = t0 + s * gridDim.x;
        if (ts < ntiles) issue_tile(ts, s);
        cp_commit();
    }

    int it = 0;
    for (int t = t0; t < ntiles; t += gridDim.x, it++) {
        int buf = it & (NSTAGE - 1);
        int tn = t + (NSTAGE - 1) * gridDim.x;
        if (tn < ntiles) issue_tile(tn, (it + NSTAGE - 1) & (NSTAGE - 1));
        cp_commit();
        cp_wait3();            // tile t's group retired (3 newer pending)
        __syncthreads();       // also covers one-time Wc staging on iter 0

        int base = t * TILE;
        float* bx = sx + buf * TILE * SXS;
        int* bt_ = stid + buf * TILE;
        unsigned abase = sx_u + (unsigned)(buf * TILE * SXS) * 4u + a_off;

        // ---- init accumulators from gathered tissue keys (bias pre-folded) ----
        float acc[2][4];
        {
            int tlo = bt_[rlo] & (MAX_TISSUE - 1);
            int thi = bt_[rhi] & (MAX_TISSUE - 1);
            const float2* klo = (const float2*)&g_tkb[(size_t)tlo * HID];
            const float2* khi = (const float2*)&g_tkb[(size_t)thi * HID];
            #pragma unroll
            for (int nt = 0; nt < 2; nt++) {
                float2 a = klo[wn * 8 + nt * 4 + tig];
                float2 b = khi[wn * 8 + nt * 4 + tig];
                acc[nt][0] = a.x; acc[nt][1] = a.y;
                acc[nt][2] = b.x; acc[nt][3] = b.y;
            }
        }

        // ---- Q += X @ Wc^T via ldmatrix + mma.sync m16n8k8 tf32 ----
        #pragma unroll
        for (int p = 0; p < 8; p++) {
            unsigned a0[4], a1[4];
            ldm_x4(a0, abase + (unsigned)(p * 64));        // kk = 2p
            ldm_x4(a1, abase + (unsigned)(p * 64 + 32));   // kk = 2p+1
            #pragma unroll
            for (int nt = 0; nt < 2; nt++) {
                unsigned b[4];
                ldm_x4(b, b_off + (unsigned)(nt * 8 * SWS) * 4u + (unsigned)(p * 64));
                asm volatile(
                    "mma.sync.aligned.m16n8k8.row.col.f32.tf32.tf32.f32 "
                    "{%0,%1,%2,%3}, {%4,%5,%6,%7}, {%8,%9}, {%0,%1,%2,%3};\n"
                    : "+f"(acc[nt][0]), "+f"(acc[nt][1]),
                      "+f"(acc[nt][2]), "+f"(acc[nt][3])
                    : "r"(a0[0]), "r"(a0[1]), "r"(a0[2]), "r"(a0[3]),
                      "r"(b[0]), "r"(b[1]));
                asm volatile(
                    "mma.sync.aligned.m16n8k8.row.col.f32.tf32.tf32.f32 "
                    "{%0,%1,%2,%3}, {%4,%5,%6,%7}, {%8,%9}, {%0,%1,%2,%3};\n"
                    : "+f"(acc[nt][0]), "+f"(acc[nt][1]),
                      "+f"(acc[nt][2]), "+f"(acc[nt][3])
                    : "r"(a1[0]), "r"(a1[1]), "r"(a1[2]), "r"(a1[3]),
                      "r"(b[2]), "r"(b[3]));
            }
        }

        // ---- partial score = attn . tanh(acc) over this warp's 16 cols ----
        float p0 = 0.f, p1 = 0.f;
        #pragma unroll
        for (int nt = 0; nt < 2; nt++) {
            float aw0 = sattn[h0 + nt * 8 + tig * 2];
            float aw1 = sattn[h0 + nt * 8 + tig * 2 + 1];
            p0 += aw0 * tanh_ap(acc[nt][0]) + aw1 * tanh_ap(acc[nt][1]);
            p1 += aw0 * tanh_ap(acc[nt][2]) + aw1 * tanh_ap(acc[nt][3]);
        }
        p0 += __shfl_xor_sync(0xffffffffu, p0, 1);
        p0 += __shfl_xor_sync(0xffffffffu, p0, 2);
        p1 += __shfl_xor_sync(0xffffffffu, p1, 1);
        p1 += __shfl_xor_sync(0xffffffffu, p1, 2);
        if (tig == 0) {
            spart[wn * TILE + rlo] = p0;
            spart[wn * TILE + rhi] = p1;
        }
        __syncthreads();

        // ---- epilogue: gate inline; out = x + tissue[t]*gate (streaming) ----
        #pragma unroll
        for (int j = 0; j < 4; j++) {
            int i = tid + j * 256;
            int r = i >> 5, c = i & 31;
            int row = base + r;
            if (row >= n_cell) continue;
            float s = spart[r] + spart[TILE + r]
                    + spart[2 * TILE + r] + spart[3 * TILE + r];
            float g = __fdividef(1.f, 1.f + __expf(-s));
            float4 xv = *(const float4*)&bx[r * SXS + c * 4];
            int tt = bt_[r];
            float4 tv = ((const float4*)tissuef)[(size_t)tt * 32 + c];
            float4 o;
            o.x = fmaf(tv.x, g, xv.x);
            o.y = fmaf(tv.y, g, xv.y);
            o.z = fmaf(tv.z, g, xv.z);
            o.w = fmaf(tv.w, g, xv.w);
            __stcs(&((float4*)out)[(size_t)row * 32 + c], o);
        }
        __syncthreads();   // buffer reusable NSTAGE-1 iterations from now
    }
}

// ---------------------------------------------------------------------------
extern "C" void kernel_launch(void* const* d_in, const int* in_sizes, int n_in,
                              void* d_out, int out_size) {
    const float* cellf   = (const float*)d_in[0];
    const float* tissuef = (const float*)d_in[1];
    const int*   c2t     = (const int*)d_in[2];
    const float* Wt      = (const float*)d_in[3];
    const float* bt      = (const float*)d_in[4];
    const float* Wc      = (const float*)d_in[5];
    const float* bc      = (const float*)d_in[6];
    const float* attnw   = (const float*)d_in[7];
    float* out = (float*)d_out;

    int n_cell   = in_sizes[0] / DIM;
    int n_tissue = in_sizes[1] / DIM;
    int ntiles   = (n_cell + TILE - 1) / TILE;

    tissue_proj_kernel<<<(n_tissue + 15) / 16, 256>>>(tissuef, Wt, bt, bc, n_tissue);

    int dev = 0, sms = 148;
    cudaGetDevice(&dev);
    cudaDeviceGetAttribute(&sms, cudaDevAttrMultiProcessorCount, dev);

    size_t shmem_bytes =
        (size_t)(NSTAGE * TILE * SXS + 64 * SWS) * 4   // X stages + Wc
        + (NSTAGE * TILE) * 4                           // stid
        + (4 * TILE) * 4                                // spart
        + 64 * 4;                                       // sattn
    cudaFuncSetAttribute(fuse_kernel,
                         cudaFuncAttributeMaxDynamicSharedMemorySize,
                         (int)shmem_bytes);
    int grid = 2 * sms;
    if (grid > ntiles) grid = ntiles;
    fuse_kernel<<<grid, 256, shmem_bytes>>>(cellf, tissuef, c2t, Wc, attnw,
                                            out, n_cell, ntiles);
}

// round 13
// speedup vs baseline: 1.5001x; 1.3670x over previous
#include <cuda_runtime.h>
#include <cstdint>

#define DIM 128
#define HID 64
#define MAX_TISSUE 4096
#define TILE 32
#define SXS 132  // padded float stride, X tile
#define SWS 132  // padded float stride, Wc staging (tf32 bits)

// scratch: projected tissue keys (+ both biases folded in)
__device__ float g_tkb[MAX_TISSUE * HID];

// ---------------------------------------------------------------------------
// Kernel A: tkb[t][h] = bt[h] + bc[h] + sum_d Wt[h][d] * tissue[t][d]
// ---------------------------------------------------------------------------
__global__ void tissue_proj_kernel(const float* __restrict__ tissue,
                                   const float* __restrict__ Wt,
                                   const float* __restrict__ bt,
                                   const float* __restrict__ bc,
                                   int n_tissue) {
    __shared__ float st[16][DIM];
    __shared__ float swt[HID][DIM + 4];
    int tid = threadIdx.x;
    int t0 = blockIdx.x * 16;

    for (int i = tid; i < HID * (DIM / 4); i += 256) {
        int h = i >> 5, c = i & 31;
        float4 v = ((const float4*)Wt)[h * 32 + c];
        *(float4*)&swt[h][c * 4] = v;
    }
    for (int i = tid; i < 16 * 32; i += 256) {
        int r = i >> 5, c = i & 31;
        float4 v = make_float4(0.f, 0.f, 0.f, 0.f);
        if (t0 + r < n_tissue) v = ((const float4*)tissue)[(size_t)(t0 + r) * 32 + c];
        *(float4*)&st[r][c * 4] = v;
    }
    __syncthreads();

    #pragma unroll
    for (int j = 0; j < 4; j++) {
        int o = tid + j * 256;
        int tl = o >> 6, h = o & 63;
        if (t0 + tl >= n_tissue) continue;
        float acc = bt[h] + bc[h];
        #pragma unroll 8
        for (int c = 0; c < 32; c++) {
            float4 w = *(const float4*)&swt[h][c * 4];
            float4 x = *(const float4*)&st[tl][c * 4];
            acc += w.x * x.x + w.y * x.y + w.z * x.z + w.w * x.w;
        }
        g_tkb[(size_t)(t0 + tl) * HID + h] = acc;
    }
}

// ---------------------------------------------------------------------------
__device__ __forceinline__ unsigned f2tf32(float x) {
    unsigned r;
    asm("cvt.rna.tf32.f32 %0, %1;" : "=r"(r) : "f"(x));
    return r;
}
__device__ __forceinline__ float tanh_ap(float x) {
    float y;
    asm("tanh.approx.f32 %0, %1;" : "=f"(y) : "f"(x));
    return y;
}
__device__ __forceinline__ void cp_async16(void* sdst, const void* gsrc, bool pred) {
    unsigned s = (unsigned)__cvta_generic_to_shared(sdst);
    int sz = pred ? 16 : 0;
    asm volatile("cp.async.cg.shared.global [%0], [%1], 16, %2;\n"
                 :: "r"(s), "l"(gsrc), "r"(sz));
}
__device__ __forceinline__ void cp_async4(void* sdst, const void* gsrc, bool pred) {
    unsigned s = (unsigned)__cvta_generic_to_shared(sdst);
    int sz = pred ? 4 : 0;
    asm volatile("cp.async.ca.shared.global [%0], [%1], 4, %2;\n"
                 :: "r"(s), "l"(gsrc), "r"(sz));
}
__device__ __forceinline__ void cp_commit() {
    asm volatile("cp.async.commit_group;\n" ::: "memory");
}
__device__ __forceinline__ void cp_wait0() {
    asm volatile("cp.async.wait_group 0;\n" ::: "memory");
}
__device__ __forceinline__ void cp_wait1() {
    asm volatile("cp.async.wait_group 1;\n" ::: "memory");
}
__device__ __forceinline__ void ldm_x4(unsigned* r, unsigned saddr) {
    asm volatile("ldmatrix.sync.aligned.m8n8.x4.shared.b16 {%0,%1,%2,%3}, [%4];"
                 : "=r"(r[0]), "=r"(r[1]), "=r"(r[2]), "=r"(r[3])
                 : "r"(saddr));
}

extern __shared__ float smem[];

// ---------------------------------------------------------------------------
// Kernel B: persistent; 32-row tiles; 2 CTAs/SM; B (Wc) register-resident;
// TISSUE GATHER STAGED VIA cp.async (overlapped with mma) — no exposed
// epilogue gmem gather. Warp grid: 2 m-tiles x 4 n-quarters.
// ---------------------------------------------------------------------------
__global__ __launch_bounds__(256, 2)
void fuse_kernel(const float* __restrict__ cellf,
                 const float* __restrict__ tissuef,
                 const int* __restrict__ c2t,
                 const float* __restrict__ Wc,
                 const float* __restrict__ attnw,
                 float* __restrict__ out,
                 int n_cell, int ntiles) {
    float*    sx    = smem;                      // 2 X buffers, 32*132 each
    unsigned* swc   = (unsigned*)smem;           // ALIAS: Wc staging (prologue)
    float*    stis  = smem + 2 * TILE * SXS;     // tissue stage, 32*128
    int*      stid  = (int*)(stis + TILE * DIM); // 2 buffers, 32 each
    float*    spart = (float*)(stid + 2 * TILE); // 4 * 32 partials
    float*    sattn = spart + 4 * TILE;          // 64

    int tid = threadIdx.x;
    int wid = tid >> 5, lane = tid & 31;
    int gid = lane >> 2, tig = lane & 3;
    int wm = wid & 1, wn = wid >> 1;     // 2 m-tiles x 4 n-quarters
    int m0 = wm * 16;
    int rlo = m0 + gid, rhi = m0 + gid + 8;
    int h0 = wn * 16;

    int lml = lane & 7, lmm = lane >> 3;
    unsigned sx_u = (unsigned)__cvta_generic_to_shared(sx);
    unsigned a_off = ((unsigned)((m0 + (lmm & 1) * 8 + lml) * SXS + (lmm >> 1) * 4)) * 4u;
    unsigned b_off = sx_u + ((unsigned)((h0 + lml) * SWS + lmm * 4)) * 4u;

    // ---- prologue: stage Wc tf32 into aliased smem, extract B to regs ----
    for (int i = tid; i < 64 * 32; i += 256) {
        int r = i >> 5, c = i & 31;
        float4 v = ((const float4*)Wc)[r * 32 + c];
        uint4 w;
        w.x = f2tf32(v.x); w.y = f2tf32(v.y); w.z = f2tf32(v.z); w.w = f2tf32(v.w);
        *(uint4*)&swc[r * SWS + c * 4] = w;
    }
    if (tid < 64) sattn[tid] = attnw[tid];
    __syncthreads();

    unsigned breg[2][8][4];   // loop-invariant B fragments (64 regs)
    #pragma unroll
    for (int nt = 0; nt < 2; nt++)
        #pragma unroll
        for (int p = 0; p < 8; p++)
            ldm_x4(breg[nt][p],
                   b_off + (unsigned)(nt * 8 * SWS) * 4u + (unsigned)(p * 64));
    __syncthreads();          // Wc staging region now reusable as X buffers

    // ---- X-tile + ids issue helper ----
    auto issue_x = [&](int t, int buf) {
        float* dst = sx + buf * TILE * SXS;
        int base = t * TILE;
        #pragma unroll
        for (int j = 0; j < 4; j++) {
            int i = tid + j * 256;
            int r = i >> 5, c = i & 31;
            int row = base + r;
            bool ok = row < n_cell;
            int rowc = ok ? row : (n_cell - 1);
            cp_async16(&dst[r * SXS + c * 4],
                       cellf + (size_t)rowc * DIM + c * 4, ok);
        }
        if (tid < TILE) {
            int row = base + tid;
            bool ok = row < n_cell;
            int rowc = ok ? row : 0;
            cp_async4(&stid[buf * TILE + tid], c2t + rowc, ok);
        }
    };

    int t0 = blockIdx.x;
    if (t0 < ntiles) issue_x(t0, 0);
    cp_commit();                        // pending: {X(t0)}

    int it = 0;
    for (int t = t0; t < ntiles; t += gridDim.x, it++) {
        int buf = it & 1;
        cp_wait0();                     // X(t) + ids(t) resident
        __syncthreads();                // stid visible; buffers safe

        int base = t * TILE;
        int* bt_ = stid + buf * TILE;

        // ---- stage tissue rows for tile t (overlaps with mma below) ----
        #pragma unroll
        for (int j = 0; j < 4; j++) {
            int i = tid + j * 256;
            int r = i >> 5, c = i & 31;
            int row = base + r;
            bool ok = row < n_cell;
            int tt = bt_[r] & (MAX_TISSUE - 1);
            cp_async16(&stis[r * DIM + c * 4],
                       tissuef + (size_t)tt * DIM + c * 4, ok);
        }
        cp_commit();                    // T(t)   [older]

        // ---- issue X(t+1) ----
        int tn = t + gridDim.x;
        if (tn < ntiles) issue_x(tn, buf ^ 1);
        cp_commit();                    // X(t+1) [newest]

        float* bx = sx + buf * TILE * SXS;
        unsigned abase = sx_u + (unsigned)(buf * TILE * SXS) * 4u + a_off;

        // ---- init accumulators from gathered tissue keys (bias pre-folded) ----
        float acc[2][4];
        {
            int tlo = bt_[rlo] & (MAX_TISSUE - 1);
            int thi = bt_[rhi] & (MAX_TISSUE - 1);
            const float2* klo = (const float2*)&g_tkb[(size_t)tlo * HID];
            const float2* khi = (const float2*)&g_tkb[(size_t)thi * HID];
            #pragma unroll
            for (int nt = 0; nt < 2; nt++) {
                float2 a = klo[wn * 8 + nt * 4 + tig];
                float2 b = khi[wn * 8 + nt * 4 + tig];
                acc[nt][0] = a.x; acc[nt][1] = a.y;
                acc[nt][2] = b.x; acc[nt][3] = b.y;
            }
        }

        // ---- Q += X @ Wc^T : ldmatrix A; B from registers ----
        #pragma unroll
        for (int p = 0; p < 8; p++) {
            unsigned a0[4], a1[4];
            ldm_x4(a0, abase + (unsigned)(p * 64));        // kk = 2p
            ldm_x4(a1, abase + (unsigned)(p * 64 + 32));   // kk = 2p+1
            #pragma unroll
            for (int nt = 0; nt < 2; nt++) {
                asm volatile(
                    "mma.sync.aligned.m16n8k8.row.col.f32.tf32.tf32.f32 "
                    "{%0,%1,%2,%3}, {%4,%5,%6,%7}, {%8,%9}, {%0,%1,%2,%3};\n"
                    : "+f"(acc[nt][0]), "+f"(acc[nt][1]),
                      "+f"(acc[nt][2]), "+f"(acc[nt][3])
                    : "r"(a0[0]), "r"(a0[1]), "r"(a0[2]), "r"(a0[3]),
                      "r"(breg[nt][p][0]), "r"(breg[nt][p][1]));
                asm volatile(
                    "mma.sync.aligned.m16n8k8.row.col.f32.tf32.tf32.f32 "
                    "{%0,%1,%2,%3}, {%4,%5,%6,%7}, {%8,%9}, {%0,%1,%2,%3};\n"
                    : "+f"(acc[nt][0]), "+f"(acc[nt][1]),
                      "+f"(acc[nt][2]), "+f"(acc[nt][3])
                    : "r"(a1[0]), "r"(a1[1]), "r"(a1[2]), "r"(a1[3]),
                      "r"(breg[nt][p][2]), "r"(breg[nt][p][3]));
            }
        }

        // ---- partial score = attn . tanh(acc) over this warp's 16 cols ----
        float p0 = 0.f, p1 = 0.f;
        #pragma unroll
        for (int nt = 0; nt < 2; nt++) {
            float aw0 = sattn[h0 + nt * 8 + tig * 2];
            float aw1 = sattn[h0 + nt * 8 + tig * 2 + 1];
            p0 += aw0 * tanh_ap(acc[nt][0]) + aw1 * tanh_ap(acc[nt][1]);
            p1 += aw0 * tanh_ap(acc[nt][2]) + aw1 * tanh_ap(acc[nt][3]);
        }
        p0 += __shfl_xor_sync(0xffffffffu, p0, 1);
        p0 += __shfl_xor_sync(0xffffffffu, p0, 2);
        p1 += __shfl_xor_sync(0xffffffffu, p1, 1);
        p1 += __shfl_xor_sync(0xffffffffu, p1, 2);
        if (tig == 0) {
            spart[wn * TILE + rlo] = p0;
            spart[wn * TILE + rhi] = p1;
        }

        cp_wait1();                     // T(t) retired (X(t+1) may still fly)
        __syncthreads();                // spart + stis visible

        // ---- epilogue: gate inline; out = x + tissue_staged * gate ----
        #pragma unroll
        for (int j = 0; j < 4; j++) {
            int i = tid + j * 256;
            int r = i >> 5, c = i & 31;
            int row = base + r;
            if (row >= n_cell) continue;
            float s = spart[r] + spart[TILE + r]
                    + spart[2 * TILE + r] + spart[3 * TILE + r];
            float g = __fdividef(1.f, 1.f + __expf(-s));
            float4 xv = *(const float4*)&bx[r * SXS + c * 4];
            float4 tv = *(const float4*)&stis[r * DIM + c * 4];
            float4 o;
            o.x = fmaf(tv.x, g, xv.x);
            o.y = fmaf(tv.y, g, xv.y);
            o.z = fmaf(tv.z, g, xv.z);
            o.w = fmaf(tv.w, g, xv.w);
            ((float4*)out)[(size_t)row * 32 + c] = o;
        }
        // next iteration's cp_wait0 + __syncthreads fences buffer reuse
    }
}

// ---------------------------------------------------------------------------
extern "C" void kernel_launch(void* const* d_in, const int* in_sizes, int n_in,
                              void* d_out, int out_size) {
    const float* cellf   = (const float*)d_in[0];
    const float* tissuef = (const float*)d_in[1];
    const int*   c2t     = (const int*)d_in[2];
    const float* Wt      = (const float*)d_in[3];
    const float* bt      = (const float*)d_in[4];
    const float* Wc      = (const float*)d_in[5];
    const float* bc      = (const float*)d_in[6];
    const float* attnw   = (const float*)d_in[7];
    float* out = (float*)d_out;

    int n_cell   = in_sizes[0] / DIM;
    int n_tissue = in_sizes[1] / DIM;
    int ntiles   = (n_cell + TILE - 1) / TILE;

    tissue_proj_kernel<<<(n_tissue + 15) / 16, 256>>>(tissuef, Wt, bt, bc, n_tissue);

    int dev = 0, sms = 148;
    cudaGetDevice(&dev);
    cudaDeviceGetAttribute(&sms, cudaDevAttrMultiProcessorCount, dev);

    size_t shmem_bytes =
        (size_t)(2 * TILE * SXS) * 4    // X buffers (aliased Wc staging)
        + (size_t)(TILE * DIM) * 4      // tissue stage
        + (2 * TILE) * 4                // stid
        + (4 * TILE) * 4                // spart
        + 64 * 4;                       // sattn
    cudaFuncSetAttribute(fuse_kernel,
                         cudaFuncAttributeMaxDynamicSharedMemorySize,
                         (int)shmem_bytes);
    int grid = 2 * sms;
    if (grid > ntiles) grid = ntiles;
    fuse_kernel<<<grid, 256, shmem_bytes>>>(cellf, tissuef, c2t, Wc, attnw,
                                            out, n_cell, ntiles);
}